// round 17
// baseline (speedup 1.0000x reference)
#include <cuda_runtime.h>
#include <cuda_bf16.h>
#include <cstdint>

#define HH 16
#define SS 2048
#define DD 128
#define BM 128
#define BN 64
#define NT 256
#define NELEM (2 * HH * SS * DD)

// ---- device scratch: split K and transposed-split V (bf16 hi/lo) ----
__device__ __nv_bfloat16 g_Khi[NELEM];
__device__ __nv_bfloat16 g_Klo[NELEM];
__device__ __nv_bfloat16 g_VThi[NELEM];   // [bh][d][s]
__device__ __nv_bfloat16 g_VTlo[NELEM];

// ---- main-kernel smem layout (bytes) ----
#define OFF_AMCX 0                     // 2 bufs x (am 256B + cx 256B)
#define OFF_QHI  1024                  // 128 rows x 256B
#define OFF_QLO  33792
#define OFF_KV   66560                 // 2 bufs x 64KB: [KHI 16K][KLO 16K][VHI 16K][VLO 16K]
#define SMEM_TOTAL 197632

__device__ __forceinline__ uint32_t smem_u32(const void* p){
    uint32_t a;
    asm("{ .reg .u64 t; cvta.to.shared.u64 t, %1; cvt.u32.u64 %0, t; }" : "=r"(a) : "l"(p));
    return a;
}
__device__ __forceinline__ void split2(float x, float y, uint32_t& hi, uint32_t& lo){
    __nv_bfloat162 h = __floats2bfloat162_rn(x, y);
    __nv_bfloat162 l = __floats2bfloat162_rn(x - __bfloat162float(h.x), y - __bfloat162float(h.y));
    hi = *reinterpret_cast<uint32_t*>(&h);
    lo = *reinterpret_cast<uint32_t*>(&l);
}
__device__ __forceinline__ void mma_bf16(float* d, const uint32_t* a, uint32_t b0, uint32_t b1){
    asm("mma.sync.aligned.m16n8k16.row.col.f32.bf16.bf16.f32 "
        "{%0,%1,%2,%3}, {%4,%5,%6,%7}, {%8,%9}, {%0,%1,%2,%3};"
        : "+f"(d[0]), "+f"(d[1]), "+f"(d[2]), "+f"(d[3])
        : "r"(a[0]), "r"(a[1]), "r"(a[2]), "r"(a[3]), "r"(b0), "r"(b1));
}
__device__ __forceinline__ void ldsm4(uint32_t* r, uint32_t addr){
    asm volatile("ldmatrix.sync.aligned.m8n8.x4.shared.b16 {%0,%1,%2,%3}, [%4];"
        : "=r"(r[0]), "=r"(r[1]), "=r"(r[2]), "=r"(r[3]) : "r"(addr));
}
__device__ __forceinline__ void cpa16(uint32_t dst, const void* src){
    asm volatile("cp.async.cg.shared.global [%0], [%1], 16;" :: "r"(dst), "l"(src));
}
__device__ __forceinline__ void cpa8(uint32_t dst, const void* src){
    asm volatile("cp.async.ca.shared.global [%0], [%1], 8;" :: "r"(dst), "l"(src));
}
#define CP_COMMIT() asm volatile("cp.async.commit_group;" ::: "memory")
#define CP_WAIT0()  asm volatile("cp.async.wait_group 0;" ::: "memory")
#define CP_WAIT1()  asm volatile("cp.async.wait_group 1;" ::: "memory")

// =================== prepass kernels ===================
__global__ void prep_k_kernel(const float* __restrict__ K){
    size_t i = (size_t)blockIdx.x * 256 + threadIdx.x;   // float4 index
    float4 v = ((const float4*)K)[i];
    uint32_t h0, l0, h1, l1;
    split2(v.x, v.y, h0, l0);
    split2(v.z, v.w, h1, l1);
    ((uint2*)g_Khi)[i] = make_uint2(h0, h1);
    ((uint2*)g_Klo)[i] = make_uint2(l0, l1);
}
__global__ void prep_v_kernel(const float* __restrict__ V){
    __shared__ float ts[32][33];
    const int bh = blockIdx.z, d0 = blockIdx.y * 32, s0 = blockIdx.x * 32;
    const int t = threadIdx.x, i = t >> 3, j4 = (t & 7) * 4;
    const float* Vp = V + ((size_t)bh * SS + s0) * DD + d0;
    float4 v = *(const float4*)(Vp + (size_t)i * DD + j4);
    ts[i][j4] = v.x; ts[i][j4 + 1] = v.y; ts[i][j4 + 2] = v.z; ts[i][j4 + 3] = v.w;
    __syncthreads();
    float a = ts[j4][i], b = ts[j4 + 1][i], c = ts[j4 + 2][i], d = ts[j4 + 3][i];
    uint32_t h0, l0, h1, l1;
    split2(a, b, h0, l0);
    split2(c, d, h1, l1);
    size_t dst = ((size_t)bh * DD + d0 + i) * SS + s0 + j4;
    *(uint2*)(g_VThi + dst) = make_uint2(h0, h1);
    *(uint2*)(g_VTlo + dst) = make_uint2(l0, l1);
}

// =================== main kernel helpers ===================
__device__ __forceinline__ void issue_loads(const __nv_bfloat16* Khb, const __nv_bfloat16* Klb,
                                            const __nv_bfloat16* Vhb, const __nv_bfloat16* Vlb,
                                            const float* AM, const float* CTX, size_t bS,
                                            int kbase, int buf, uint32_t sb, int tid)
{
    const uint32_t kv = sb + OFF_KV + (uint32_t)buf * 65536u;
    #pragma unroll
    for (int i = 0; i < 4; ++i){                      // K: 64 rows x 16 chunks
        int flat = tid + i * NT;
        int r = flat >> 4, c = flat & 15;
        uint32_t o = (uint32_t)r * 256u + ((((uint32_t)c) ^ ((uint32_t)r & 7u)) << 4);
        cpa16(kv + o,          (const char*)(Khb + (size_t)(kbase + r) * DD) + c * 16);
        cpa16(kv + 16384u + o, (const char*)(Klb + (size_t)(kbase + r) * DD) + c * 16);
    }
    #pragma unroll
    for (int i = 0; i < 4; ++i){                      // VT: 128 rows x 8 chunks
        int flat = tid + i * NT;
        int d = flat >> 3, c = flat & 7;
        uint32_t o = (uint32_t)d * 128u + ((((uint32_t)c) ^ ((uint32_t)d & 7u)) << 4);
        cpa16(kv + 32768u + o, (const char*)(Vhb + (size_t)d * SS + kbase) + c * 16);
        cpa16(kv + 49152u + o, (const char*)(Vlb + (size_t)d * SS + kbase) + c * 16);
    }
    if (tid < 32)       cpa8(sb + OFF_AMCX + buf * 512 + tid * 8,              AM  + bS + kbase + 2 * tid);
    else if (tid < 64)  cpa8(sb + OFF_AMCX + buf * 512 + 256 + (tid - 32) * 8, CTX + bS + kbase + 2 * (tid - 32));
    CP_COMMIT();
}

// QK for 2 key-blocks (np0, np0+1), skipping fully-masked blocks (16*np > qrel)
__device__ __forceinline__ void qk_half(float (*sacc)[4], uint32_t qbh, uint32_t qbl,
                                        uint32_t kvb, int np0, uint32_t swA, uint32_t hi4,
                                        int rB, uint32_t cof, int qrel)
{
    if (16 * np0 > qrel) return;                      // whole half masked
    const bool np1ok = (16 * (np0 + 1) <= qrel);
    #pragma unroll
    for (int kb = 0; kb < 8; ++kb){
        uint32_t ah[4], al[4];
        uint32_t coff = (((uint32_t)(2 * kb) + hi4) ^ swA) << 4;
        ldsm4(ah, qbh + coff);
        ldsm4(al, qbl + coff);
        uint32_t bh4[2][4], bl4[2][4];
        {
            int rowB = 16 * np0 + rB;
            uint32_t ko = (uint32_t)rowB * 256u
                        + ((((uint32_t)(2 * kb) + cof) ^ ((uint32_t)rowB & 7u)) << 4);
            ldsm4(bh4[0], kvb + ko);
            ldsm4(bl4[0], kvb + 16384u + ko);
        }
        if (np1ok){
            int rowB = 16 * (np0 + 1) + rB;
            uint32_t ko = (uint32_t)rowB * 256u
                        + ((((uint32_t)(2 * kb) + cof) ^ ((uint32_t)rowB & 7u)) << 4);
            ldsm4(bh4[1], kvb + ko);
            ldsm4(bl4[1], kvb + 16384u + ko);
        }
        mma_bf16(sacc[0], ah, bh4[0][0], bh4[0][1]);
        mma_bf16(sacc[1], ah, bh4[0][2], bh4[0][3]);
        mma_bf16(sacc[0], ah, bl4[0][0], bl4[0][1]);
        mma_bf16(sacc[1], ah, bl4[0][2], bl4[0][3]);
        mma_bf16(sacc[0], al, bh4[0][0], bh4[0][1]);
        mma_bf16(sacc[1], al, bh4[0][2], bh4[0][3]);
        if (np1ok){
            mma_bf16(sacc[2], ah, bh4[1][0], bh4[1][1]);
            mma_bf16(sacc[3], ah, bh4[1][2], bh4[1][3]);
            mma_bf16(sacc[2], ah, bl4[1][0], bl4[1][1]);
            mma_bf16(sacc[3], ah, bl4[1][2], bl4[1][3]);
            mma_bf16(sacc[2], al, bh4[1][0], bh4[1][1]);
            mma_bf16(sacc[3], al, bh4[1][2], bh4[1][3]);
        }
    }
}

// softmax for j in [j0, j0+4), skipping j-pairs whose 16-key block is masked
__device__ __forceinline__ void softmax_half(const float (*sacc)[4], uint32_t (*PH)[2], uint32_t (*PL)[2],
                                             const float* amb, const float* cxb, int j0,
                                             int kbase, int colt, int qg0, int qg1,
                                             float& z0t, float& z1t, int qrel)
{
    #pragma unroll
    for (int jj = 0; jj < 4; ++jj){
        int j = j0 + jj;
        if (8 * (j & ~1) > qrel) continue;            // matching PV block skipped too
        int col = kbase + 8 * j + colt;
        float2 am2 = *(const float2*)&amb[8 * j + colt];
        float2 cx2 = *(const float2*)&cxb[8 * j + colt];
        float p0 = (col     <= qg0) ? __expf(sacc[jj][0] + am2.x) : 0.f;
        float p1 = (col + 1 <= qg0) ? __expf(sacc[jj][1] + am2.y) : 0.f;
        float p2 = (col     <= qg1) ? __expf(sacc[jj][2] + am2.x) : 0.f;
        float p3 = (col + 1 <= qg1) ? __expf(sacc[jj][3] + am2.y) : 0.f;
        z0t += p0 + p1;  z1t += p2 + p3;              // Z uses UNSCALED p
        p0 *= cx2.x; p1 *= cx2.y;                     // ctx applied post-softmax
        p2 *= cx2.x; p3 *= cx2.y;
        split2(p0, p1, PH[jj][0], PL[jj][0]);
        split2(p2, p3, PH[jj][1], PL[jj][1]);
    }
}

// PV for kb in [kb0, kb0+2), skipping masked 16-key blocks
__device__ __forceinline__ void pv_half(float (*oacc)[4], const uint32_t (*PH)[2], const uint32_t (*PL)[2],
                                        uint32_t kvb, int kb0, int rB, uint32_t cof, int qrel)
{
    if (16 * kb0 > qrel) return;
    #pragma unroll
    for (int k2 = 0; k2 < 2; ++k2){
        int kb = kb0 + k2;
        if (16 * kb > qrel) continue;
        uint32_t Ahf[4] = {PH[2 * k2][0], PH[2 * k2][1], PH[2 * k2 + 1][0], PH[2 * k2 + 1][1]};
        uint32_t Alf[4] = {PL[2 * k2][0], PL[2 * k2][1], PL[2 * k2 + 1][0], PL[2 * k2 + 1][1]};
        #pragma unroll
        for (int hg = 0; hg < 2; ++hg){
            uint32_t vh[4][4], vl[4][4];
            #pragma unroll
            for (int q = 0; q < 4; ++q){
                int rowV = 16 * (4 * hg + q) + rB;
                uint32_t vo = (uint32_t)rowV * 128u
                            + ((((uint32_t)(2 * kb) + cof) ^ ((uint32_t)rowV & 7u)) << 4);
                ldsm4(vh[q], kvb + 32768u + vo);
                ldsm4(vl[q], kvb + 49152u + vo);
            }
            #pragma unroll
            for (int q = 0; q < 4; ++q){               // Ph x Vh
                int np = 4 * hg + q;
                mma_bf16(oacc[2 * np],     Ahf, vh[q][0], vh[q][1]);
                mma_bf16(oacc[2 * np + 1], Ahf, vh[q][2], vh[q][3]);
            }
            #pragma unroll
            for (int q = 0; q < 4; ++q){               // Ph x Vl
                int np = 4 * hg + q;
                mma_bf16(oacc[2 * np],     Ahf, vl[q][0], vl[q][1]);
                mma_bf16(oacc[2 * np + 1], Ahf, vl[q][2], vl[q][3]);
            }
            #pragma unroll
            for (int q = 0; q < 4; ++q){               // Pl x Vh
                int np = 4 * hg + q;
                mma_bf16(oacc[2 * np],     Alf, vh[q][0], vh[q][1]);
                mma_bf16(oacc[2 * np + 1], Alf, vh[q][2], vh[q][3]);
            }
        }
    }
}

__global__ __launch_bounds__(NT, 1)
void attn_hmma_kernel(const float* __restrict__ Q,
                      const float* __restrict__ AM,
                      const float* __restrict__ HM,
                      const float* __restrict__ CTX,
                      float* __restrict__ out)
{
    extern __shared__ char sm[];
    const uint32_t sb = smem_u32(sm);
    const int tid = threadIdx.x, wid = tid >> 5, lane = tid & 31;

    const int it = (gridDim.x - 1) - blockIdx.x;   // heavy q-tiles first
    const int h = blockIdx.y, b = blockIdx.z;
    const int bh = b * HH + h;
    const int q0 = it * BM;
    const int nt = 2 * (it + 1);

    const float* Qp = Q + ((size_t)bh * SS + q0) * DD;
    const __nv_bfloat16* Khb = g_Khi  + (size_t)bh * SS * DD;
    const __nv_bfloat16* Klb = g_Klo  + (size_t)bh * SS * DD;
    const __nv_bfloat16* Vhb = g_VThi + (size_t)bh * SS * DD;
    const __nv_bfloat16* Vlb = g_VTlo + (size_t)bh * SS * DD;
    const size_t bS = (size_t)b * SS;

    // ---- prologue: start tile-0 streaming, overlap with Q load+split ----
    issue_loads(Khb, Klb, Vhb, Vlb, AM, CTX, bS, 0, 0, sb, tid);
    {
        const float4* Qg = (const float4*)Qp;
        #pragma unroll
        for (int i = 0; i < 16; ++i){
            int flat = tid + i * NT;
            int r = flat >> 5, g = flat & 31;
            float4 v = Qg[flat];
            uint32_t h0, l0, h1, l1;
            split2(v.x, v.y, h0, l0);
            split2(v.z, v.w, h1, l1);
            uint32_t o = (uint32_t)r * 256u
                       + ((((uint32_t)(g >> 1)) ^ ((uint32_t)r & 7u)) << 4)
                       + (((uint32_t)(g & 1)) << 3);
            *(uint2*)(sm + OFF_QHI + o) = make_uint2(h0, h1);
            *(uint2*)(sm + OFF_QLO + o) = make_uint2(l0, l1);
        }
    }

    const int rowA = 16 * wid + (lane & 15);
    const uint32_t qbh = sb + OFF_QHI + rowA * 256;
    const uint32_t qbl = sb + OFF_QLO + rowA * 256;
    const uint32_t swA = rowA & 7, hi4 = lane >> 4;
    const int rB  = (lane & 7) + ((lane >> 4) & 1) * 8;
    const uint32_t cof = (lane >> 3) & 1;

    const int g    = lane >> 2;
    const int colt = 2 * (lane & 3);
    const int qg0 = q0 + 16 * wid + g;
    const int qg1 = qg0 + 8;
    const bool grpA = (wid < 4);      // w and w+4 share an SMSP: give them opposite phase

    float oacc[16][4];
    #pragma unroll
    for (int i = 0; i < 16; ++i)
        #pragma unroll
        for (int j = 0; j < 4; ++j) oacc[i][j] = 0.f;
    float z0t = 0.f, z1t = 0.f;

    for (int jt = 0; jt < nt; ++jt){
        const int kbase = jt * BN;
        const int cur = jt & 1;
        const uint32_t kvb = sb + OFF_KV + (uint32_t)cur * 65536u;

        __syncthreads();      // all warps done reading buf cur^1 (tile jt-1)
        if (jt + 1 < nt){
            issue_loads(Khb, Klb, Vhb, Vlb, AM, CTX, bS, (jt + 1) * BN, cur ^ 1, sb, tid);
            CP_WAIT1();       // tile jt complete (jt+1 may stay in flight)
        } else {
            CP_WAIT0();
        }
        __syncthreads();      // tile jt visible to all threads

        // triangular causal skip: qrel = highest in-tile key this warp attends to
        const int qrel = q0 + 16 * wid + 15 - kbase;
        if (qrel < 0) continue;                         // whole warp-block masked

        const float* amb = (const float*)(sm + OFF_AMCX + cur * 512);
        const float* cxb = amb + 64;

        float sacc[8][4];
        #pragma unroll
        for (int i = 0; i < 8; ++i)
            #pragma unroll
            for (int j = 0; j < 4; ++j) sacc[i][j] = 0.f;

        uint32_t PH[8][2], PL[8][2];

        // Staggered schedules: SMSP warp pairs (w, w+4) run complementary phases.
        qk_half(sacc,     qbh, qbl, kvb, 0, swA, hi4, rB, cof, qrel);
        if (grpA)
            softmax_half(sacc, PH, PL, amb, cxb, 0, kbase, colt, qg0, qg1, z0t, z1t, qrel);
        qk_half(sacc + 4, qbh, qbl, kvb, 2, swA, hi4, rB, cof, qrel);
        if (grpA){
            pv_half(oacc, PH, PL, kvb, 0, rB, cof, qrel);
            softmax_half(sacc + 4, PH + 4, PL + 4, amb, cxb, 4, kbase, colt, qg0, qg1, z0t, z1t, qrel);
        } else {
            softmax_half(sacc,     PH,     PL,     amb, cxb, 0, kbase, colt, qg0, qg1, z0t, z1t, qrel);
            softmax_half(sacc + 4, PH + 4, PL + 4, amb, cxb, 4, kbase, colt, qg0, qg1, z0t, z1t, qrel);
            pv_half(oacc, PH, PL, kvb, 0, rB, cof, qrel);
        }
        pv_half(oacc, PH + 4, PL + 4, kvb, 2, rB, cof, qrel);
    }

    // ---- epilogue: reduce Z across lane quads, /Z, * head_mask, store ----
    z0t += __shfl_xor_sync(0xffffffffu, z0t, 1);
    z0t += __shfl_xor_sync(0xffffffffu, z0t, 2);
    z1t += __shfl_xor_sync(0xffffffffu, z1t, 1);
    z1t += __shfl_xor_sync(0xffffffffu, z1t, 2);

    const float hm = HM[h];
    const float i0 = hm / z0t, i1 = hm / z1t;
    float* O0 = out + ((size_t)bh * SS + q0 + 16 * wid + g) * DD;
    float* O1 = O0 + 8 * DD;
    #pragma unroll
    for (int nb = 0; nb < 16; ++nb){
        *(float2*)&O0[8 * nb + colt] = make_float2(oacc[nb][0] * i0, oacc[nb][1] * i0);
        *(float2*)&O1[8 * nb + colt] = make_float2(oacc[nb][2] * i1, oacc[nb][3] * i1);
    }
}

extern "C" void kernel_launch(void* const* d_in, const int* in_sizes, int n_in,
                              void* d_out, int out_size)
{
    (void)in_sizes; (void)n_in; (void)out_size;
    const float* Q   = (const float*)d_in[0];
    const float* K   = (const float*)d_in[1];
    const float* V   = (const float*)d_in[2];
    const float* AM  = (const float*)d_in[3];
    const float* HM  = (const float*)d_in[4];
    const float* CTX = (const float*)d_in[5];
    float* out = (float*)d_out;

    cudaFuncSetAttribute(attn_hmma_kernel,
                         cudaFuncAttributeMaxDynamicSharedMemorySize, SMEM_TOTAL);

    prep_k_kernel<<<NELEM / 4 / 256, 256>>>(K);
    prep_v_kernel<<<dim3(SS / 32, DD / 32, 2 * HH), 256>>>(V);

    dim3 grid(SS / BM, HH, 2);
    attn_hmma_kernel<<<grid, NT, SMEM_TOTAL>>>(Q, AM, HM, CTX, out);
}